// round 9
// baseline (speedup 1.0000x reference)
#include <cuda_runtime.h>
#include <cstdint>
#include <math.h>

// CapsuleLayer collapses (routing b never updates) to:
//   out = squash_z1( r(h,w) * denseconv5x5(x[4,64,128,128], W[128,64,5,5], pad=2) )
//   r(h,w) = 1 / (8 * cntH(h) * cntW(w))
// tf32 mma.sync implicit GEMM. R7: ldmatrix fragment loads (replaces 96 scalar
// LDS/warp/stage with 6 LDSM.x4), B re-laid-out n-major for LDSM.

// ------------------------- device scratch -------------------------
__device__ float g_Xp[4 * 128 * 128 * 64];   // NHWC, tf32-rounded (16 MB)
__device__ float g_Wp[25 * 2 * 128 * 32];    // [off][chunk][oc][ci], tf32-rounded

__device__ __forceinline__ float tf32_rna(float x) {
    uint32_t r;
    asm("cvt.rna.tf32.f32 %0, %1;" : "=r"(r) : "f"(x));
    return __uint_as_float(r);
}

__device__ __forceinline__ uint32_t smem_u32(const void* p) {
    uint32_t a;
    asm("{ .reg .u64 t; cvta.to.shared.u64 t, %1; cvt.u32.u64 %0, t; }"
        : "=r"(a) : "l"(p));
    return a;
}

__device__ __forceinline__ void cp_async16(uint32_t dst, const void* src, uint32_t src_sz) {
    asm volatile("cp.async.cg.shared.global [%0], [%1], 16, %2;"
                 :: "r"(dst), "l"(src), "r"(src_sz) : "memory");
}
__device__ __forceinline__ void cp_commit() {
    asm volatile("cp.async.commit_group;" ::: "memory");
}
template <int N>
__device__ __forceinline__ void cp_wait() {
    asm volatile("cp.async.wait_group %0;" :: "n"(N) : "memory");
}

__device__ __forceinline__ void ldsm_x4(uint32_t& r0, uint32_t& r1, uint32_t& r2,
                                        uint32_t& r3, uint32_t addr) {
    asm volatile("ldmatrix.sync.aligned.m8n8.x4.shared.b16 {%0,%1,%2,%3}, [%4];"
                 : "=r"(r0), "=r"(r1), "=r"(r2), "=r"(r3) : "r"(addr));
}

__device__ __forceinline__ void mma_tf32(float& d0, float& d1, float& d2, float& d3,
                                         uint32_t a0, uint32_t a1, uint32_t a2, uint32_t a3,
                                         uint32_t b0, uint32_t b1) {
    asm volatile(
        "mma.sync.aligned.m16n8k8.row.col.f32.tf32.tf32.f32 "
        "{%0,%1,%2,%3}, {%4,%5,%6,%7}, {%8,%9}, {%0,%1,%2,%3};"
        : "+f"(d0), "+f"(d1), "+f"(d2), "+f"(d3)
        : "r"(a0), "r"(a1), "r"(a2), "r"(a3), "r"(b0), "r"(b1));
}

// ------------------------- merged prep kernel -------------------------
// blocks [0,2048):   u [4,64,128,128] NCHW -> g_Xp [4,128,128,64] NHWC (tf32)
// blocks [2048,2848): W [4,128,16,5,5]     -> g_Wp[((off*2+chunk)*128+oc)*32+ci]
__global__ void prep_kernel(const float* __restrict__ u, const float* __restrict__ W) {
    __shared__ float tile[64][33];
    int tid = threadIdx.x;                // 256
    if (blockIdx.x < 2048) {
        int blk = blockIdx.x;
        int wt = blk & 3;
        int h = (blk >> 2) & 127;
        int n = blk >> 9;
        int lw = tid & 31, lc = tid >> 5;
#pragma unroll
        for (int r = 0; r < 8; ++r) {
            int c = r * 8 + lc;
            float v = u[(((n << 6) + c) << 14) + (h << 7) + (wt << 5) + lw];
            tile[c][lw] = tf32_rna(v);
        }
        __syncthreads();
        int cc = tid & 63, lw2 = tid >> 6;
#pragma unroll
        for (int r = 0; r < 8; ++r) {
            int wl = r * 4 + lw2;
            int w = (wt << 5) + wl;
            g_Xp[((((n << 7) + h) << 7) + w) * 64 + cc] = tile[cc][wl];
        }
    } else {
        int idx = (blockIdx.x - 2048) * 256 + tid;   // 204800 total
        int ci    = idx & 31;
        int oc    = (idx >> 5) & 127;
        int chunk = (idx >> 12) & 1;
        int off   = idx >> 13;
        int c = chunk * 32 + ci;
        int t0 = c >> 4, z0 = c & 15;
        g_Wp[idx] = tf32_rna(W[((t0 * 128 + oc) * 16 + z0) * 25 + off]);
    }
}

// ------------------------- main GEMM kernel -------------------------
// Grid: 256 CTAs. CTA = (n = b>>6, h0 = (b&63)*2). M=256 px (2 rows x 128 w),
// N=128 oc, K = 50 stages of 32 (25 offsets x 2 ci-chunks).
// 512 threads = 16 warps (4x4), warp tile 64x32. 4-stage ring, prefetch 2.
// Fragments via ldmatrix.x4: A rows=pixels (pitch 144B), B rows=oc (pitch 144B).

static constexpr int NSTAGES = 50;
static constexpr int RING = 4;
static constexpr int PITCH_F = 36;                       // floats per smem row
static constexpr int PITCH_B = PITCH_F * 4;              // 144 bytes
static constexpr int A_STAGE_F = 256 * PITCH_F;          // 9216 floats
static constexpr int B_STAGE_F = 128 * PITCH_F;          // 4608 floats
static constexpr uint32_t A_STAGE_BYTES = A_STAGE_F * 4;
static constexpr uint32_t B_STAGE_BYTES = B_STAGE_F * 4;
static constexpr uint32_t SMEM_BYTES = RING * (A_STAGE_BYTES + B_STAGE_BYTES);  // 221184

__global__ void __launch_bounds__(512, 1) conv_main_kernel(float* __restrict__ out) {
    extern __shared__ float smem[];
    uint32_t smem_base = smem_u32(smem);

    int tid = threadIdx.x;
    int lane = tid & 31;
    int wid = tid >> 5;
    int wm = wid >> 2, wn = wid & 3;
    int b = blockIdx.x;
    int n = b >> 6;
    int h0 = (b & 63) << 1;

    float acc[4][4][4];
#pragma unroll
    for (int i = 0; i < 4; ++i)
#pragma unroll
        for (int j = 0; j < 4; ++j)
#pragma unroll
            for (int k = 0; k < 4; ++k) acc[i][j][k] = 0.f;

    // ldmatrix lane addressing: sel = lane>>3 (matrix id), r = lane&7.
    // row block = (sel&1)*8 + r, 16B-col = sel>>1.
    int rowoff = ((lane >> 3) & 1) * 8 + (lane & 7);
    int col16 = lane >> 4;
    uint32_t a_lane = (uint32_t)((wm * 64 + rowoff) * PITCH_B + col16 * 16);
    uint32_t b_lane = (uint32_t)((wn * 32 + rowoff) * PITCH_B + col16 * 16);

    // ---- stage loader: s -> (ky, chunk, kx) ----
    auto load_stage = [&](int s) {
        int buf = s & (RING - 1);
        int ky = s / 10;
        int rem = s - ky * 10;
        int chunk = rem / 5;
        int kx = rem - chunk * 5;
        int off = ky * 5 + kx;
        uint32_t aB = smem_base + (uint32_t)buf * A_STAGE_BYTES;
        uint32_t bB = smem_base + RING * A_STAGE_BYTES + (uint32_t)buf * B_STAGE_BYTES;
        // A: 256 pixels x 32 ci = 2048 x 16B, 4 per thread
#pragma unroll
        for (int i = 0; i < 4; ++i) {
            int idx = tid + i * 512;
            int m = idx >> 3, seg = idx & 7;
            int r = m >> 7, w = m & 127;
            int hh = h0 + r + ky - 2;
            int ww = w + kx - 2;
            const float* src = g_Xp + ((((n << 7) + hh) << 7) + ww) * 64 + chunk * 32 + seg * 4;
            uint32_t ok = ((unsigned)hh < 128u && (unsigned)ww < 128u) ? 16u : 0u;
            cp_async16(aB + (uint32_t)(m * PITCH_B + seg * 16), src, ok);
        }
        // B: 128 oc x 32 ci = 1024 x 16B, 2 per thread (n-major rows)
#pragma unroll
        for (int i = 0; i < 2; ++i) {
            int idx = tid + i * 512;
            int oc = idx >> 3, seg = idx & 7;
            const float* src = g_Wp + (((off * 2 + chunk) * 128 + oc) << 5) + seg * 4;
            cp_async16(bB + (uint32_t)(oc * PITCH_B + seg * 16), src, 16u);
        }
        cp_commit();
    };

    load_stage(0);
    load_stage(1);

    for (int s = 0; s < NSTAGES; ++s) {
        if (s + 2 < NSTAGES) {
            load_stage(s + 2);
            cp_wait<2>();
        } else if (s + 1 < NSTAGES) {
            cp_wait<1>();
        } else {
            cp_wait<0>();
        }
        __syncthreads();

        uint32_t aS = smem_base + (uint32_t)(s & (RING - 1)) * A_STAGE_BYTES + a_lane;
        uint32_t bS = smem_base + RING * A_STAGE_BYTES +
                      (uint32_t)(s & (RING - 1)) * B_STAGE_BYTES + b_lane;
#pragma unroll
        for (int ks = 0; ks < 4; ++ks) {
            uint32_t af[4][4], bfr[2][4];
#pragma unroll
            for (int mf = 0; mf < 4; ++mf)
                ldsm_x4(af[mf][0], af[mf][1], af[mf][2], af[mf][3],
                        aS + (uint32_t)(mf * 16 * PITCH_B + ks * 32));
#pragma unroll
            for (int nfp = 0; nfp < 2; ++nfp)
                ldsm_x4(bfr[nfp][0], bfr[nfp][1], bfr[nfp][2], bfr[nfp][3],
                        bS + (uint32_t)(nfp * 16 * PITCH_B + ks * 32));
#pragma unroll
            for (int mf = 0; mf < 4; ++mf)
#pragma unroll
                for (int nf = 0; nf < 4; ++nf)
                    mma_tf32(acc[mf][nf][0], acc[mf][nf][1], acc[mf][nf][2], acc[mf][nf][3],
                             af[mf][0], af[mf][1], af[mf][2], af[mf][3],
                             bfr[nf >> 1][nf & 1], bfr[nf >> 1][2 + (nf & 1)]);
        }
    }

    // ---- epilogue: r(h,w) scale + squash over z1 (16 cols) + store ----
#pragma unroll
    for (int mf = 0; mf < 4; ++mf) {
#pragma unroll
        for (int half = 0; half < 2; ++half) {
            int m = wm * 64 + mf * 16 + half * 8 + (lane >> 2);
            int h = h0 + (m >> 7);
            int w = m & 127;
            int cntH = min(h + 2, 127) - max(h - 2, 0) + 1;
            int cntW = min(w + 2, 127) - max(w - 2, 0) + 1;
            float rr = 1.f / (8.f * (float)(cntH * cntW));
#pragma unroll
            for (int grp = 0; grp < 2; ++grp) {
                float v0 = acc[mf][grp * 2][half * 2];
                float v1 = acc[mf][grp * 2][half * 2 + 1];
                float v2 = acc[mf][grp * 2 + 1][half * 2];
                float v3 = acc[mf][grp * 2 + 1][half * 2 + 1];
                float ssum = v0 * v0 + v1 * v1 + v2 * v2 + v3 * v3;
                ssum += __shfl_xor_sync(0xffffffffu, ssum, 1);
                ssum += __shfl_xor_sync(0xffffffffu, ssum, 2);
                float n2 = rr * rr * ssum;
                float sc = rr * n2 / ((1.f + n2) * sqrtf(n2 + 1e-9f));
                int t1 = wn * 2 + grp;
                int z0 = (lane & 3) * 2;
                float* ob = out + (((n * 8 + t1) * 16) << 14) + (h << 7) + w;
                ob[(z0 + 0) << 14] = v0 * sc;
                ob[(z0 + 1) << 14] = v1 * sc;
                ob[(z0 + 8) << 14] = v2 * sc;
                ob[(z0 + 9) << 14] = v3 * sc;
            }
        }
    }
}

// ------------------------- launch -------------------------
extern "C" void kernel_launch(void* const* d_in, const int* in_sizes, int n_in,
                              void* d_out, int out_size) {
    const float* u = (const float*)d_in[0];   // [4,4,16,128,128]
    const float* W = (const float*)d_in[1];   // [4,128,16,5,5]
    float* out = (float*)d_out;               // [4,8,16,128,128]
    (void)in_sizes; (void)n_in; (void)out_size;

    cudaFuncSetAttribute(conv_main_kernel,
                         cudaFuncAttributeMaxDynamicSharedMemorySize, SMEM_BYTES);

    prep_kernel<<<2848, 256>>>(u, W);
    conv_main_kernel<<<256, 512, SMEM_BYTES>>>(out);
}

// round 13
// speedup vs baseline: 1.2333x; 1.2333x over previous
#include <cuda_runtime.h>
#include <cstdint>
#include <math.h>

// CapsuleLayer collapses (routing b never updates) to:
//   out = squash_z1( r(h,w) * denseconv5x5(x[4,64,128,128], W[128,64,5,5], pad=2) )
//   r(h,w) = 1 / (8 * cntH(h) * cntW(w))
// tf32 mma.sync implicit GEMM.
// R10: A slab resident in smem (loaded once per ci-chunk, halo zero-filled);
//      each of the 25 offsets is a shifted ldmatrix view. Only B (16KB) cycles
//      through a 4-slot cp.async ring. Per-stage ALU/LSU overhead ~gone.

// ------------------------- device scratch -------------------------
__device__ float g_Xp[4 * 128 * 128 * 64];   // NHWC, tf32-rounded (16 MB)
__device__ float g_Wp[25 * 2 * 128 * 32];    // [off][chunk][oc][ci], tf32-rounded

__device__ __forceinline__ float tf32_rna(float x) {
    uint32_t r;
    asm("cvt.rna.tf32.f32 %0, %1;" : "=r"(r) : "f"(x));
    return __uint_as_float(r);
}

__device__ __forceinline__ uint32_t smem_u32(const void* p) {
    uint32_t a;
    asm("{ .reg .u64 t; cvta.to.shared.u64 t, %1; cvt.u32.u64 %0, t; }"
        : "=r"(a) : "l"(p));
    return a;
}

__device__ __forceinline__ void cp_async16(uint32_t dst, const void* src, uint32_t src_sz) {
    asm volatile("cp.async.cg.shared.global [%0], [%1], 16, %2;"
                 :: "r"(dst), "l"(src), "r"(src_sz) : "memory");
}
__device__ __forceinline__ void cp_commit() {
    asm volatile("cp.async.commit_group;" ::: "memory");
}
template <int N>
__device__ __forceinline__ void cp_wait() {
    asm volatile("cp.async.wait_group %0;" :: "n"(N) : "memory");
}

__device__ __forceinline__ void ldsm_x4(uint32_t& r0, uint32_t& r1, uint32_t& r2,
                                        uint32_t& r3, uint32_t addr) {
    asm volatile("ldmatrix.sync.aligned.m8n8.x4.shared.b16 {%0,%1,%2,%3}, [%4];"
                 : "=r"(r0), "=r"(r1), "=r"(r2), "=r"(r3) : "r"(addr));
}

__device__ __forceinline__ void mma_tf32(float& d0, float& d1, float& d2, float& d3,
                                         uint32_t a0, uint32_t a1, uint32_t a2, uint32_t a3,
                                         uint32_t b0, uint32_t b1) {
    asm volatile(
        "mma.sync.aligned.m16n8k8.row.col.f32.tf32.tf32.f32 "
        "{%0,%1,%2,%3}, {%4,%5,%6,%7}, {%8,%9}, {%0,%1,%2,%3};"
        : "+f"(d0), "+f"(d1), "+f"(d2), "+f"(d3)
        : "r"(a0), "r"(a1), "r"(a2), "r"(a3), "r"(b0), "r"(b1));
}

// ------------------------- merged prep kernel -------------------------
// blocks [0,2048):   u [4,64,128,128] NCHW -> g_Xp [4,128,128,64] NHWC (tf32)
// blocks [2048,2848): W [4,128,16,5,5]     -> g_Wp[((off*2+chunk)*128+oc)*32+ci]
__global__ void prep_kernel(const float* __restrict__ u, const float* __restrict__ W) {
    __shared__ float tile[64][33];
    int tid = threadIdx.x;                // 256
    if (blockIdx.x < 2048) {
        int blk = blockIdx.x;
        int wt = blk & 3;
        int h = (blk >> 2) & 127;
        int n = blk >> 9;
        int lw = tid & 31, lc = tid >> 5;
#pragma unroll
        for (int r = 0; r < 8; ++r) {
            int c = r * 8 + lc;
            float v = u[(((n << 6) + c) << 14) + (h << 7) + (wt << 5) + lw];
            tile[c][lw] = tf32_rna(v);
        }
        __syncthreads();
        int cc = tid & 63, lw2 = tid >> 6;
#pragma unroll
        for (int r = 0; r < 8; ++r) {
            int wl = r * 4 + lw2;
            int w = (wt << 5) + wl;
            g_Xp[((((n << 7) + h) << 7) + w) * 64 + cc] = tile[cc][wl];
        }
    } else {
        int idx = (blockIdx.x - 2048) * 256 + tid;   // 204800 total
        int ci    = idx & 31;
        int oc    = (idx >> 5) & 127;
        int chunk = (idx >> 12) & 1;
        int off   = idx >> 13;
        int c = chunk * 32 + ci;
        int t0 = c >> 4, z0 = c & 15;
        g_Wp[idx] = tf32_rna(W[((t0 * 128 + oc) * 16 + z0) * 25 + off]);
    }
}

// ------------------------- main GEMM kernel -------------------------
// Grid: 256 CTAs. CTA = (n = b>>6, h0 = (b&63)*2). M=256 px (2 rows x 128 w),
// N=128 oc. 2 ci-chunk passes x 25 offsets.
// A slab: 6 input rows x 132 halo-cols x 32 ci, pitch 144B/pixel (bank-free for
// LDSM). B ring: 4 x (128 oc x 32 ci), pitch 144B/oc-row.
// 512 threads = 16 warps (4x4), warp tile 64 px x 32 oc.

static constexpr int PITCH_B = 144;                 // bytes per smem row
static constexpr int A_COLS = 132;                  // halo cols (w -2..129)
static constexpr int A_ROW_BYTES = A_COLS * PITCH_B;        // 19008
static constexpr uint32_t A_BYTES = 6 * A_ROW_BYTES;        // 114048
static constexpr uint32_t B_STAGE_BYTES = 128 * PITCH_B;    // 18432
static constexpr uint32_t SMEM_BYTES = A_BYTES + 4 * B_STAGE_BYTES;  // 187776

__global__ void __launch_bounds__(512, 1) conv_main_kernel(float* __restrict__ out) {
    extern __shared__ float smem[];
    uint32_t A_base = smem_u32(smem);
    uint32_t B_base = A_base + A_BYTES;

    int tid = threadIdx.x;
    int lane = tid & 31;
    int wid = tid >> 5;
    int wm = wid >> 2, wn = wid & 3;
    int b = blockIdx.x;
    int n = b >> 6;
    int h0 = (b & 63) << 1;

    float acc[4][4][4];
#pragma unroll
    for (int i = 0; i < 4; ++i)
#pragma unroll
        for (int j = 0; j < 4; ++j)
#pragma unroll
            for (int k = 0; k < 4; ++k) acc[i][j][k] = 0.f;

    // ldmatrix lane addressing (verified by passing R9):
    int rowoff = ((lane >> 3) & 1) * 8 + (lane & 7);
    int col16 = lane >> 4;
    int r_warp = wm >> 1;                   // image row within CTA (0/1)
    int w0 = (wm & 1) * 64;                 // pixel col base of warp tile
    uint32_t a_lane = (uint32_t)(r_warp * A_ROW_BYTES +
                                 (w0 + rowoff) * PITCH_B + col16 * 16);
    uint32_t b_lane = (uint32_t)((wn * 32 + rowoff) * PITCH_B + col16 * 16);

    // ---- A slab loader (once per chunk): 6336 x 16B ops ----
    auto load_A = [&](int chunk) {
#pragma unroll
        for (int i = 0; i < 13; ++i) {
            int idx = tid + i * 512;
            if (idx < 6336) {
                int a = idx / 1056;                 // smem row 0..5
                int rem = idx - a * 1056;
                int c = rem >> 3, seg = rem & 7;    // halo col, 16B seg
                int hi = h0 + a - 2;
                int wi = c - 2;
                const float* src = g_Xp + ((((n << 7) + hi) << 7) + wi) * 64 +
                                   chunk * 32 + seg * 4;
                uint32_t ok = ((unsigned)hi < 128u && (unsigned)wi < 128u) ? 16u : 0u;
                cp_async16(A_base + (uint32_t)(a * A_ROW_BYTES + c * PITCH_B + seg * 16),
                           src, ok);
            }
        }
        cp_commit();
    };

    // ---- B stage loader: s = chunk*25 + off ----
    auto load_B = [&](int s, int off, int chunk) {
        uint32_t bB = B_base + (uint32_t)(s & 3) * B_STAGE_BYTES;
        const float* wsrc = g_Wp + (size_t)(off * 2 + chunk) * 4096;
#pragma unroll
        for (int i = 0; i < 2; ++i) {
            int idx = tid + i * 512;
            int oc = idx >> 3, seg = idx & 7;
            cp_async16(bB + (uint32_t)(oc * PITCH_B + seg * 16),
                       wsrc + oc * 32 + seg * 4, 16u);
        }
        cp_commit();
    };

    for (int chunk = 0; chunk < 2; ++chunk) {
        if (chunk) __syncthreads();    // all warps done reading previous A slab
        load_A(chunk);
        load_B(chunk * 25 + 0, 0, chunk);
        load_B(chunk * 25 + 1, 1, chunk);

        int ky = 0, kx = 0;
        for (int off = 0; off < 25; ++off) {
            int s = chunk * 25 + off;
            if (off + 2 < 25) {
                load_B(s + 2, off + 2, chunk);
                cp_wait<2>();          // A slab (+B up to off) complete
            } else if (off + 1 < 25) {
                cp_wait<1>();
            } else {
                cp_wait<0>();
            }
            __syncthreads();

            uint32_t aS = A_base + a_lane + (uint32_t)(ky * A_ROW_BYTES + kx * PITCH_B);
            uint32_t bS = B_base + (uint32_t)(s & 3) * B_STAGE_BYTES + b_lane;
#pragma unroll
            for (int ks = 0; ks < 4; ++ks) {
                uint32_t af[4][4], bfr[2][4];
#pragma unroll
                for (int mf = 0; mf < 4; ++mf)
                    ldsm_x4(af[mf][0], af[mf][1], af[mf][2], af[mf][3],
                            aS + (uint32_t)(mf * 16 * PITCH_B + ks * 32));
#pragma unroll
                for (int nfp = 0; nfp < 2; ++nfp)
                    ldsm_x4(bfr[nfp][0], bfr[nfp][1], bfr[nfp][2], bfr[nfp][3],
                            bS + (uint32_t)(nfp * 16 * PITCH_B + ks * 32));
#pragma unroll
                for (int mf = 0; mf < 4; ++mf)
#pragma unroll
                    for (int nf = 0; nf < 4; ++nf)
                        mma_tf32(acc[mf][nf][0], acc[mf][nf][1], acc[mf][nf][2], acc[mf][nf][3],
                                 af[mf][0], af[mf][1], af[mf][2], af[mf][3],
                                 bfr[nf >> 1][nf & 1], bfr[nf >> 1][2 + (nf & 1)]);
            }
            if (++kx == 5) { kx = 0; ++ky; }
        }
    }

    // ---- epilogue: r(h,w) scale + squash over z1 (16 cols) + store ----
#pragma unroll
    for (int mf = 0; mf < 4; ++mf) {
#pragma unroll
        for (int half = 0; half < 2; ++half) {
            int m = wm * 64 + mf * 16 + half * 8 + (lane >> 2);
            int h = h0 + (m >> 7);
            int w = m & 127;
            int cntH = min(h + 2, 127) - max(h - 2, 0) + 1;
            int cntW = min(w + 2, 127) - max(w - 2, 0) + 1;
            float rr = 1.f / (8.f * (float)(cntH * cntW));
#pragma unroll
            for (int grp = 0; grp < 2; ++grp) {
                float v0 = acc[mf][grp * 2][half * 2];
                float v1 = acc[mf][grp * 2][half * 2 + 1];
                float v2 = acc[mf][grp * 2 + 1][half * 2];
                float v3 = acc[mf][grp * 2 + 1][half * 2 + 1];
                float ssum = v0 * v0 + v1 * v1 + v2 * v2 + v3 * v3;
                ssum += __shfl_xor_sync(0xffffffffu, ssum, 1);
                ssum += __shfl_xor_sync(0xffffffffu, ssum, 2);
                float n2 = rr * rr * ssum;
                float sc = rr * n2 / ((1.f + n2) * sqrtf(n2 + 1e-9f));
                int t1 = wn * 2 + grp;
                int z0 = (lane & 3) * 2;
                float* ob = out + (((n * 8 + t1) * 16) << 14) + (h << 7) + w;
                ob[(z0 + 0) << 14] = v0 * sc;
                ob[(z0 + 1) << 14] = v1 * sc;
                ob[(z0 + 8) << 14] = v2 * sc;
                ob[(z0 + 9) << 14] = v3 * sc;
            }
        }
    }
}

// ------------------------- launch -------------------------
extern "C" void kernel_launch(void* const* d_in, const int* in_sizes, int n_in,
                              void* d_out, int out_size) {
    const float* u = (const float*)d_in[0];   // [4,4,16,128,128]
    const float* W = (const float*)d_in[1];   // [4,128,16,5,5]
    float* out = (float*)d_out;               // [4,8,16,128,128]
    (void)in_sizes; (void)n_in; (void)out_size;

    cudaFuncSetAttribute(conv_main_kernel,
                         cudaFuncAttributeMaxDynamicSharedMemorySize, SMEM_BYTES);

    prep_kernel<<<2848, 256>>>(u, W);
    conv_main_kernel<<<256, 512, SMEM_BYTES>>>(out);
}

// round 14
// speedup vs baseline: 2.1711x; 1.7603x over previous
#include <cuda_runtime.h>
#include <cuda_fp16.h>
#include <cstdint>
#include <math.h>

// CapsuleLayer collapses (routing b never updates) to:
//   out = squash_z1( r(h,w) * denseconv5x5(x[4,64,128,128], W[128,64,5,5], pad=2) )
//   r(h,w) = 1 / (8 * cntH(h) * cntW(w))
// R14: fp16 m16n8k16 mma (2x tensor rate of tf32, same 10-bit mantissa).
//   A slab (6 rows x 132 halo-cols x 64 ci fp16) resident in smem, loaded ONCE;
//   25 offset-stages (one barrier each), B (128oc x 64ci fp16) in 4-slot ring.

// ------------------------- device scratch -------------------------
__device__ __half g_Xp[4 * 128 * 128 * 64];   // NHWC fp16 (8 MB)
__device__ __half g_Wp[25 * 128 * 64];        // [off][oc][ci] fp16

__device__ __forceinline__ uint32_t smem_u32(const void* p) {
    uint32_t a;
    asm("{ .reg .u64 t; cvta.to.shared.u64 t, %1; cvt.u32.u64 %0, t; }"
        : "=r"(a) : "l"(p));
    return a;
}

__device__ __forceinline__ void cp_async16(uint32_t dst, const void* src, uint32_t src_sz) {
    asm volatile("cp.async.cg.shared.global [%0], [%1], 16, %2;"
                 :: "r"(dst), "l"(src), "r"(src_sz) : "memory");
}
__device__ __forceinline__ void cp_commit() {
    asm volatile("cp.async.commit_group;" ::: "memory");
}
template <int N>
__device__ __forceinline__ void cp_wait() {
    asm volatile("cp.async.wait_group %0;" :: "n"(N) : "memory");
}

__device__ __forceinline__ void ldsm_x4(uint32_t& r0, uint32_t& r1, uint32_t& r2,
                                        uint32_t& r3, uint32_t addr) {
    asm volatile("ldmatrix.sync.aligned.m8n8.x4.shared.b16 {%0,%1,%2,%3}, [%4];"
                 : "=r"(r0), "=r"(r1), "=r"(r2), "=r"(r3) : "r"(addr));
}

__device__ __forceinline__ void mma_f16(float& d0, float& d1, float& d2, float& d3,
                                        uint32_t a0, uint32_t a1, uint32_t a2, uint32_t a3,
                                        uint32_t b0, uint32_t b1) {
    asm volatile(
        "mma.sync.aligned.m16n8k16.row.col.f32.f16.f16.f32 "
        "{%0,%1,%2,%3}, {%4,%5,%6,%7}, {%8,%9}, {%0,%1,%2,%3};"
        : "+f"(d0), "+f"(d1), "+f"(d2), "+f"(d3)
        : "r"(a0), "r"(a1), "r"(a2), "r"(a3), "r"(b0), "r"(b1));
}

// ------------------------- merged prep kernel -------------------------
// blocks [0,2048):   u [4,64,128,128] NCHW -> g_Xp [4,128,128,64] NHWC fp16
// blocks [2048,2848): W [4,128,16,5,5]     -> g_Wp[(off*128+oc)*64+ci] fp16
__global__ void prep_kernel(const float* __restrict__ u, const float* __restrict__ W) {
    __shared__ float tile[64][33];
    int tid = threadIdx.x;                // 256
    if (blockIdx.x < 2048) {
        int blk = blockIdx.x;
        int wt = blk & 3;
        int h = (blk >> 2) & 127;
        int n = blk >> 9;
        int lw = tid & 31, lc = tid >> 5;
#pragma unroll
        for (int r = 0; r < 8; ++r) {
            int c = r * 8 + lc;
            tile[c][lw] = u[(((n << 6) + c) << 14) + (h << 7) + (wt << 5) + lw];
        }
        __syncthreads();
        int c2 = tid & 31, lw2 = tid >> 5;
        __half2* xp2 = reinterpret_cast<__half2*>(g_Xp);
#pragma unroll
        for (int r = 0; r < 4; ++r) {
            int wl = r * 8 + lw2;
            int w = (wt << 5) + wl;
            __half2 v = __floats2half2_rn(tile[2 * c2][wl], tile[2 * c2 + 1][wl]);
            xp2[((((n << 7) + h) << 7) + w) * 32 + c2] = v;
        }
    } else {
        int idx = (blockIdx.x - 2048) * 256 + tid;   // 204800 total
        int ci  = idx & 63;
        int oc  = (idx >> 6) & 127;
        int off = idx >> 13;
        int t0 = ci >> 4, z0 = ci & 15;
        g_Wp[idx] = __float2half_rn(W[((t0 * 128 + oc) * 16 + z0) * 25 + off]);
    }
}

// ------------------------- main GEMM kernel -------------------------
// Grid: 256 CTAs. CTA = (n = b>>6, h0 = (b&63)*2). M=256 px (2 rows x 128 w),
// N=128 oc, K = 25 stages of 64 ci (one per kernel offset).
// A slab: 6 rows x 132 halo-cols x 64ci fp16, pitch 144B (conflict-free).
// B ring: 4 x (128 oc x 64ci fp16), pitch 144B. 16 warps (4x4), tile 64x32.

static constexpr int PITCH = 144;                     // bytes per smem row
static constexpr int A_COLS = 132;
static constexpr int A_ROW_BYTES = A_COLS * PITCH;            // 19008
static constexpr uint32_t A_BYTES = 6 * A_ROW_BYTES;          // 114048
static constexpr uint32_t B_STAGE_BYTES = 128 * PITCH;        // 18432
static constexpr uint32_t SMEM_BYTES = A_BYTES + 4 * B_STAGE_BYTES;  // 187776

__global__ void __launch_bounds__(512, 1) conv_main_kernel(float* __restrict__ out) {
    extern __shared__ float smem[];
    uint32_t A_base = smem_u32(smem);
    uint32_t B_base = A_base + A_BYTES;

    int tid = threadIdx.x;
    int lane = tid & 31;
    int wid = tid >> 5;
    int wm = wid >> 2, wn = wid & 3;
    int b = blockIdx.x;
    int n = b >> 6;
    int h0 = (b & 63) << 1;

    float acc[4][4][4];
#pragma unroll
    for (int i = 0; i < 4; ++i)
#pragma unroll
        for (int j = 0; j < 4; ++j)
#pragma unroll
            for (int k = 0; k < 4; ++k) acc[i][j][k] = 0.f;

    // ldmatrix lane addressing (same pattern validated in R13):
    int rowoff = ((lane >> 3) & 1) * 8 + (lane & 7);
    int col16 = lane >> 4;
    int r_warp = wm >> 1;                   // image row within CTA (0/1)
    int w0 = (wm & 1) * 64;                 // pixel col base of warp tile
    uint32_t a_lane = (uint32_t)(r_warp * A_ROW_BYTES +
                                 (w0 + rowoff) * PITCH + col16 * 16);
    uint32_t b_lane = (uint32_t)((wn * 32 + rowoff) * PITCH + col16 * 16);

    // ---- A slab loader (ONCE): 6 rows x 132 cols x 8 segs = 6336 x 16B ----
    auto load_A = [&]() {
#pragma unroll
        for (int i = 0; i < 13; ++i) {
            int idx = tid + i * 512;
            if (idx < 6336) {
                int a = idx / 1056;                 // smem row 0..5
                int rem = idx - a * 1056;
                int c = rem >> 3, seg = rem & 7;    // halo col, 16B seg (8 halves)
                int hi = h0 + a - 2;
                int wi = c - 2;
                const __half* src = g_Xp + ((((n << 7) + hi) << 7) + wi) * 64 + seg * 8;
                uint32_t ok = ((unsigned)hi < 128u && (unsigned)wi < 128u) ? 16u : 0u;
                cp_async16(A_base + (uint32_t)(a * A_ROW_BYTES + c * PITCH + seg * 16),
                           src, ok);
            }
        }
        cp_commit();
    };

    // ---- B stage loader: 128 oc x 8 segs = 1024 x 16B ----
    auto load_B = [&](int s) {
        uint32_t bB = B_base + (uint32_t)(s & 3) * B_STAGE_BYTES;
        const __half* wsrc = g_Wp + (size_t)s * 8192;   // off = s
#pragma unroll
        for (int i = 0; i < 2; ++i) {
            int idx = tid + i * 512;
            int oc = idx >> 3, seg = idx & 7;
            cp_async16(bB + (uint32_t)(oc * PITCH + seg * 16),
                       wsrc + oc * 64 + seg * 8, 16u);
        }
        cp_commit();
    };

    load_A();
    load_B(0);
    load_B(1);

    int ky = 0, kx = 0;
    for (int s = 0; s < 25; ++s) {
        if (s + 2 < 25) {
            load_B(s + 2);
            cp_wait<2>();          // A slab + B stage s complete
        } else if (s + 1 < 25) {
            cp_wait<1>();
        } else {
            cp_wait<0>();
        }
        __syncthreads();

        uint32_t aS = A_base + a_lane + (uint32_t)(ky * A_ROW_BYTES + kx * PITCH);
        uint32_t bS = B_base + (uint32_t)(s & 3) * B_STAGE_BYTES + b_lane;
#pragma unroll
        for (int ks = 0; ks < 4; ++ks) {           // 4 x k16 = 64 ci
            uint32_t af[4][4], bfr[2][4];
#pragma unroll
            for (int mf = 0; mf < 4; ++mf)
                ldsm_x4(af[mf][0], af[mf][1], af[mf][2], af[mf][3],
                        aS + (uint32_t)(mf * 16 * PITCH + ks * 32));
#pragma unroll
            for (int nfp = 0; nfp < 2; ++nfp)
                ldsm_x4(bfr[nfp][0], bfr[nfp][1], bfr[nfp][2], bfr[nfp][3],
                        bS + (uint32_t)(nfp * 16 * PITCH + ks * 32));
#pragma unroll
            for (int mf = 0; mf < 4; ++mf)
#pragma unroll
                for (int nf = 0; nf < 4; ++nf)
                    mma_f16(acc[mf][nf][0], acc[mf][nf][1], acc[mf][nf][2], acc[mf][nf][3],
                            af[mf][0], af[mf][1], af[mf][2], af[mf][3],
                            bfr[nf >> 1][nf & 1], bfr[nf >> 1][2 + (nf & 1)]);
        }
        if (++kx == 5) { kx = 0; ++ky; }
    }

    // ---- epilogue: r(h,w) scale + squash over z1 (16 cols) + store ----
#pragma unroll
    for (int mf = 0; mf < 4; ++mf) {
#pragma unroll
        for (int half = 0; half < 2; ++half) {
            int m = wm * 64 + mf * 16 + half * 8 + (lane >> 2);
            int h = h0 + (m >> 7);
            int w = m & 127;
            int cntH = min(h + 2, 127) - max(h - 2, 0) + 1;
            int cntW = min(w + 2, 127) - max(w - 2, 0) + 1;
            float rr = 1.f / (8.f * (float)(cntH * cntW));
#pragma unroll
            for (int grp = 0; grp < 2; ++grp) {
                float v0 = acc[mf][grp * 2][half * 2];
                float v1 = acc[mf][grp * 2][half * 2 + 1];
                float v2 = acc[mf][grp * 2 + 1][half * 2];
                float v3 = acc[mf][grp * 2 + 1][half * 2 + 1];
                float ssum = v0 * v0 + v1 * v1 + v2 * v2 + v3 * v3;
                ssum += __shfl_xor_sync(0xffffffffu, ssum, 1);
                ssum += __shfl_xor_sync(0xffffffffu, ssum, 2);
                float n2 = rr * rr * ssum;
                float sc = rr * n2 / ((1.f + n2) * sqrtf(n2 + 1e-9f));
                int t1 = wn * 2 + grp;
                int z0 = (lane & 3) * 2;
                float* ob = out + (((n * 8 + t1) * 16) << 14) + (h << 7) + w;
                ob[(z0 + 0) << 14] = v0 * sc;
                ob[(z0 + 1) << 14] = v1 * sc;
                ob[(z0 + 8) << 14] = v2 * sc;
                ob[(z0 + 9) << 14] = v3 * sc;
            }
        }
    }
}

// ------------------------- launch -------------------------
extern "C" void kernel_launch(void* const* d_in, const int* in_sizes, int n_in,
                              void* d_out, int out_size) {
    const float* u = (const float*)d_in[0];   // [4,4,16,128,128]
    const float* W = (const float*)d_in[1];   // [4,128,16,5,5]
    float* out = (float*)d_out;               // [4,8,16,128,128]
    (void)in_sizes; (void)n_in; (void)out_size;

    cudaFuncSetAttribute(conv_main_kernel,
                         cudaFuncAttributeMaxDynamicSharedMemorySize, SMEM_BYTES);

    prep_kernel<<<2848, 256>>>(u, W);
    conv_main_kernel<<<256, 512, SMEM_BYTES>>>(out);
}

// round 16
// speedup vs baseline: 2.2685x; 1.0449x over previous
#include <cuda_runtime.h>
#include <cuda_fp16.h>
#include <cstdint>
#include <math.h>

// CapsuleLayer collapses (routing b never updates) to:
//   out = squash_z1( r(h,w) * denseconv5x5(x[4,64,128,128], W[128,64,5,5], pad=2) )
//   r(h,w) = 1 / (8 * cntH(h) * cntW(w))
// fp16 m16n8k16 implicit GEMM. R16: same mbarrier producer/consumer pipeline
// as R15, with the deadlock fixed: cp.async.mbarrier.arrive needs .noinc so
// the async-completion arrive counts against the init count of 512 (default
// variant pre-increments the expected count -> barrier never flips -> hang).

// ------------------------- device scratch -------------------------
__device__ __half g_Xp[4 * 128 * 128 * 64];   // NHWC fp16 (8 MB)
__device__ __half g_Wp[25 * 128 * 64];        // [off][oc][ci] fp16

__device__ __forceinline__ uint32_t smem_u32(const void* p) {
    uint32_t a;
    asm("{ .reg .u64 t; cvta.to.shared.u64 t, %1; cvt.u32.u64 %0, t; }"
        : "=r"(a) : "l"(p));
    return a;
}

__device__ __forceinline__ void cp_async16(uint32_t dst, const void* src, uint32_t src_sz) {
    asm volatile("cp.async.cg.shared.global [%0], [%1], 16, %2;"
                 :: "r"(dst), "l"(src), "r"(src_sz) : "memory");
}

#define MBARRIER_INIT(addr, cnt) \
    asm volatile("mbarrier.init.shared.b64 [%0], %1;" :: "r"((uint32_t)(addr)), "r"((uint32_t)(cnt)) : "memory")

// .noinc: the completion-arrive counts against the expected count (init=512).
#define CP_ASYNC_MBAR_ARRIVE(addr) \
    asm volatile("cp.async.mbarrier.arrive.noinc.shared.b64 [%0];" :: "r"((uint32_t)(addr)) : "memory")

#define MBAR_ARRIVE(addr) \
    asm volatile("mbarrier.arrive.shared.b64 _, [%0];" :: "r"((uint32_t)(addr)) : "memory")

#define MBARRIER_WAIT_PARITY(mbar_smem_addr, phase_parity) do { \
    uint32_t _mbar = (uint32_t)(mbar_smem_addr); \
    uint32_t _parity = (uint32_t)(phase_parity); \
    uint32_t _done; \
    asm volatile( \
        "{\n\t" \
        ".reg .pred p;\n\t" \
        "mbarrier.try_wait.parity.acquire.cta.shared::cta.b64 p, [%1], %2;\n\t" \
        "selp.b32 %0, 1, 0, p;\n\t" \
        "}" \
        : "=r"(_done) : "r"(_mbar), "r"(_parity) : "memory"); \
    if (!_done) { \
        asm volatile( \
            "{\n\t" \
            ".reg .pred P1;\n\t" \
            "WAIT_LOOP_%=:\n\t" \
            "mbarrier.try_wait.parity.acquire.cta.shared::cta.b64 P1, [%0], %1, 0x989680;\n\t" \
            "@P1 bra.uni WAIT_DONE_%=;\n\t" \
            "bra.uni WAIT_LOOP_%=;\n\t" \
            "WAIT_DONE_%=:\n\t" \
            "}" \
            :: "r"(_mbar), "r"(_parity) : "memory"); \
    } \
} while (0)

__device__ __forceinline__ void ldsm_x4(uint32_t& r0, uint32_t& r1, uint32_t& r2,
                                        uint32_t& r3, uint32_t addr) {
    asm volatile("ldmatrix.sync.aligned.m8n8.x4.shared.b16 {%0,%1,%2,%3}, [%4];"
                 : "=r"(r0), "=r"(r1), "=r"(r2), "=r"(r3) : "r"(addr));
}

__device__ __forceinline__ void mma_f16(float& d0, float& d1, float& d2, float& d3,
                                        uint32_t a0, uint32_t a1, uint32_t a2, uint32_t a3,
                                        uint32_t b0, uint32_t b1) {
    asm volatile(
        "mma.sync.aligned.m16n8k16.row.col.f32.f16.f16.f32 "
        "{%0,%1,%2,%3}, {%4,%5,%6,%7}, {%8,%9}, {%0,%1,%2,%3};"
        : "+f"(d0), "+f"(d1), "+f"(d2), "+f"(d3)
        : "r"(a0), "r"(a1), "r"(a2), "r"(a3), "r"(b0), "r"(b1));
}

// ------------------------- merged prep kernel -------------------------
// blocks [0,2048):   u [4,64,128,128] NCHW -> g_Xp [4,128,128,64] NHWC fp16
// blocks [2048,2848): W [4,128,16,5,5]     -> g_Wp[(off*128+oc)*64+ci] fp16
__global__ void prep_kernel(const float* __restrict__ u, const float* __restrict__ W) {
    __shared__ float tile[64][33];
    int tid = threadIdx.x;                // 256
    if (blockIdx.x < 2048) {
        int blk = blockIdx.x;
        int wt = blk & 3;
        int h = (blk >> 2) & 127;
        int n = blk >> 9;
        int lw = tid & 31, lc = tid >> 5;
#pragma unroll
        for (int r = 0; r < 8; ++r) {
            int c = r * 8 + lc;
            tile[c][lw] = u[(((n << 6) + c) << 14) + (h << 7) + (wt << 5) + lw];
        }
        __syncthreads();
        int c2 = tid & 31, lw2 = tid >> 5;
        __half2* xp2 = reinterpret_cast<__half2*>(g_Xp);
#pragma unroll
        for (int r = 0; r < 4; ++r) {
            int wl = r * 8 + lw2;
            int w = (wt << 5) + wl;
            __half2 v = __floats2half2_rn(tile[2 * c2][wl], tile[2 * c2 + 1][wl]);
            xp2[((((n << 7) + h) << 7) + w) * 32 + c2] = v;
        }
    } else {
        int idx = (blockIdx.x - 2048) * 256 + tid;   // 204800 total
        int ci  = idx & 63;
        int oc  = (idx >> 6) & 127;
        int off = idx >> 13;
        int t0 = ci >> 4, z0 = ci & 15;
        g_Wp[idx] = __float2half_rn(W[((t0 * 128 + oc) * 16 + z0) * 25 + off]);
    }
}

// ------------------------- main GEMM kernel -------------------------
// Grid: 256 CTAs. CTA = (n = b>>6, h0 = (b&63)*2). M=256 px, N=128 oc,
// K = 25 stages of 64 ci (one per kernel offset).
// A slab: 6 rows x 132 halo-cols x 64ci fp16, pitch 144B, resident.
// B ring: 6 slots x (128 oc x 64ci fp16), full/empty mbarriers per slot.

static constexpr int PITCH = 144;                     // bytes per smem row
static constexpr int A_COLS = 132;
static constexpr int A_ROW_BYTES = A_COLS * PITCH;            // 19008
static constexpr uint32_t A_BYTES = 6 * A_ROW_BYTES;          // 114048
static constexpr uint32_t B_STAGE_BYTES = 128 * PITCH;        // 18432
static constexpr int RING = 6;
static constexpr uint32_t MBAR_BYTES = 128;
static constexpr uint32_t SMEM_BYTES = A_BYTES + RING * B_STAGE_BYTES + MBAR_BYTES; // 224768

__global__ void __launch_bounds__(512, 1) conv_main_kernel(float* __restrict__ out) {
    extern __shared__ float smem[];
    uint32_t A_base = smem_u32(smem);
    uint32_t B_base = A_base + A_BYTES;
    uint32_t M_full = B_base + RING * B_STAGE_BYTES;    // full[k] at +k*8
    uint32_t M_empty = M_full + 48;                     // empty[k] at +k*8

    int tid = threadIdx.x;
    int lane = tid & 31;
    int wid = tid >> 5;
    int wm = wid >> 2, wn = wid & 3;
    int b = blockIdx.x;
    int n = b >> 6;
    int h0 = (b & 63) << 1;

    if (tid == 0) {
#pragma unroll
        for (int k = 0; k < RING; ++k) {
            MBARRIER_INIT(M_full + k * 8, 512);
            MBARRIER_INIT(M_empty + k * 8, 512);
        }
    }
    __syncthreads();

    float acc[4][4][4];
#pragma unroll
    for (int i = 0; i < 4; ++i)
#pragma unroll
        for (int j = 0; j < 4; ++j)
#pragma unroll
            for (int k = 0; k < 4; ++k) acc[i][j][k] = 0.f;

    // ldmatrix lane addressing (validated R13/R14):
    int rowoff = ((lane >> 3) & 1) * 8 + (lane & 7);
    int col16 = lane >> 4;
    int r_warp = wm >> 1;
    int w0 = (wm & 1) * 64;
    uint32_t a_lane = (uint32_t)(r_warp * A_ROW_BYTES +
                                 (w0 + rowoff) * PITCH + col16 * 16);
    uint32_t b_lane = (uint32_t)((wn * 32 + rowoff) * PITCH + col16 * 16);

    // ---- A slab: 6 rows x 132 cols x 8 segs = 6336 x 16B cp.async ----
    auto load_A = [&]() {
#pragma unroll
        for (int i = 0; i < 13; ++i) {
            int idx = tid + i * 512;
            if (idx < 6336) {
                int a = idx / 1056;
                int rem = idx - a * 1056;
                int c = rem >> 3, seg = rem & 7;
                int hi = h0 + a - 2;
                int wi = c - 2;
                const __half* src = g_Xp + ((((n << 7) + hi) << 7) + wi) * 64 + seg * 8;
                uint32_t ok = ((unsigned)hi < 128u && (unsigned)wi < 128u) ? 16u : 0u;
                cp_async16(A_base + (uint32_t)(a * A_ROW_BYTES + c * PITCH + seg * 16),
                           src, ok);
            }
        }
    };

    // ---- B stage loader into ring slot: 1024 x 16B, 2 per thread ----
    auto load_B = [&](int s, int slot) {
        uint32_t bB = B_base + (uint32_t)slot * B_STAGE_BYTES;
        const __half* wsrc = g_Wp + (size_t)s * 8192;
#pragma unroll
        for (int i = 0; i < 2; ++i) {
            int idx = tid + i * 512;
            int oc = idx >> 3, seg = idx & 7;
            cp_async16(bB + (uint32_t)(oc * PITCH + seg * 16),
                       wsrc + oc * 64 + seg * 8, 16u);
        }
    };

    // Prologue: A (covered by full[0]'s arrive) + B stages 0..2 into slots 0..2.
    load_A();
#pragma unroll
    for (int s = 0; s < 3; ++s) {
        load_B(s, s);
        CP_ASYNC_MBAR_ARRIVE(M_full + s * 8);
    }

    int pslot = 3, pwrap = 0;   // producer tracks stage s+3
    int cslot = 0, cwrap = 0;   // consumer tracks stage s
    int ky = 0, kx = 0;
    for (int s = 0; s < 25; ++s) {
        if (s + 3 < 25) {
            if (pwrap >= 1)
                MBARRIER_WAIT_PARITY(M_empty + pslot * 8, (uint32_t)((pwrap - 1) & 1));
            load_B(s + 3, pslot);
            CP_ASYNC_MBAR_ARRIVE(M_full + pslot * 8);
            if (++pslot == RING) { pslot = 0; ++pwrap; }
        }

        MBARRIER_WAIT_PARITY(M_full + cslot * 8, (uint32_t)(cwrap & 1));

        uint32_t aS = A_base + a_lane + (uint32_t)(ky * A_ROW_BYTES + kx * PITCH);
        uint32_t bS = B_base + (uint32_t)cslot * B_STAGE_BYTES + b_lane;
#pragma unroll
        for (int ks = 0; ks < 4; ++ks) {           // 4 x k16 = 64 ci
            uint32_t af[4][4], bfr[2][4];
#pragma unroll
            for (int mf = 0; mf < 4; ++mf)
                ldsm_x4(af[mf][0], af[mf][1], af[mf][2], af[mf][3],
                        aS + (uint32_t)(mf * 16 * PITCH + ks * 32));
#pragma unroll
            for (int nfp = 0; nfp < 2; ++nfp)
                ldsm_x4(bfr[nfp][0], bfr[nfp][1], bfr[nfp][2], bfr[nfp][3],
                        bS + (uint32_t)(nfp * 16 * PITCH + ks * 32));
#pragma unroll
            for (int mf = 0; mf < 4; ++mf)
#pragma unroll
                for (int nf = 0; nf < 4; ++nf)
                    mma_f16(acc[mf][nf][0], acc[mf][nf][1], acc[mf][nf][2], acc[mf][nf][3],
                            af[mf][0], af[mf][1], af[mf][2], af[mf][3],
                            bfr[nf >> 1][nf & 1], bfr[nf >> 1][2 + (nf & 1)]);
        }

        MBAR_ARRIVE(M_empty + cslot * 8);
        if (++cslot == RING) { cslot = 0; ++cwrap; }
        if (++kx == 5) { kx = 0; ++ky; }
    }

    // ---- epilogue: r(h,w) scale + squash over z1 (16 cols) + store ----
#pragma unroll
    for (int mf = 0; mf < 4; ++mf) {
#pragma unroll
        for (int half = 0; half < 2; ++half) {
            int m = wm * 64 + mf * 16 + half * 8 + (lane >> 2);
            int h = h0 + (m >> 7);
            int w = m & 127;
            int cntH = min(h + 2, 127) - max(h - 2, 0) + 1;
            int cntW = min(w + 2, 127) - max(w - 2, 0) + 1;
            float rr = 1.f / (8.f * (float)(cntH * cntW));
#pragma unroll
            for (int grp = 0; grp < 2; ++grp) {
                float v0 = acc[mf][grp * 2][half * 2];
                float v1 = acc[mf][grp * 2][half * 2 + 1];
                float v2 = acc[mf][grp * 2 + 1][half * 2];
                float v3 = acc[mf][grp * 2 + 1][half * 2 + 1];
                float ssum = v0 * v0 + v1 * v1 + v2 * v2 + v3 * v3;
                ssum += __shfl_xor_sync(0xffffffffu, ssum, 1);
                ssum += __shfl_xor_sync(0xffffffffu, ssum, 2);
                float n2 = rr * rr * ssum;
                float sc = rr * n2 / ((1.f + n2) * sqrtf(n2 + 1e-9f));
                int t1 = wn * 2 + grp;
                int z0 = (lane & 3) * 2;
                float* ob = out + (((n * 8 + t1) * 16) << 14) + (h << 7) + w;
                ob[(z0 + 0) << 14] = v0 * sc;
                ob[(z0 + 1) << 14] = v1 * sc;
                ob[(z0 + 8) << 14] = v2 * sc;
                ob[(z0 + 9) << 14] = v3 * sc;
            }
        }
    }
}

// ------------------------- launch -------------------------
extern "C" void kernel_launch(void* const* d_in, const int* in_sizes, int n_in,
                              void* d_out, int out_size) {
    const float* u = (const float*)d_in[0];   // [4,4,16,128,128]
    const float* W = (const float*)d_in[1];   // [4,128,16,5,5]
    float* out = (float*)d_out;               // [4,8,16,128,128]
    (void)in_sizes; (void)n_in; (void)out_size;

    cudaFuncSetAttribute(conv_main_kernel,
                         cudaFuncAttributeMaxDynamicSharedMemorySize, SMEM_BYTES);

    prep_kernel<<<2848, 256>>>(u, W);
    conv_main_kernel<<<256, 512, SMEM_BYTES>>>(out);
}